// round 1
// baseline (speedup 1.0000x reference)
#include <cuda_runtime.h>

// Sliding-window minimum, window = [t, t+256] (257 elems), 'last' padding.
// out[b,t] = min_{i=t..t+256} sig[b, min(i, T-1)]
//
// Chunk-16 prefix/suffix decomposition: window len 257 = (16 - m) + 15*16 + (m+1)
// for any phase m = t % 16, so every output = min( suf16[t], 15 full-chunk mins,
// pre16[t+256] ) — exactly 17 reads, no divergence.

#define BT 256  // outputs per block / threads per block

__global__ __launch_bounds__(BT) void always_window_min(
    const float* __restrict__ sig, float* __restrict__ out, int T)
{
    const int b  = blockIdx.y;
    const int t0 = blockIdx.x * BT;          // first output index of this block
    const int tid  = threadIdx.x;
    const int lane = tid & 31;

    __shared__ float sPre[2 * BT];           // inclusive prefix-min within 16-chunk
    __shared__ float sSuf[2 * BT];           // inclusive suffix-min within 16-chunk

    const float* row = sig + (size_t)b * T;

    // Build pre/suf tables for local positions p in [0, 512): global i = t0 + p,
    // clamped to T-1 ('last' padding). lane%16 == p%16, so 16-segmented shuffles
    // align exactly with chunk boundaries.
    #pragma unroll
    for (int rep = 0; rep < 2; rep++) {
        int p = tid + rep * BT;
        int g = t0 + p;
        g = g < T - 1 ? g : T - 1;
        float x = __ldg(row + g);
        float pre = x, suf = x;
        #pragma unroll
        for (int d = 1; d < 16; d <<= 1) {
            float up = __shfl_up_sync(0xffffffffu, pre, d);
            if ((lane & 15) >= d) pre = fminf(pre, up);
            float dn = __shfl_down_sync(0xffffffffu, suf, d);
            if ((lane & 15) < 16 - d) suf = fminf(suf, dn);
        }
        sPre[p] = pre;
        sSuf[p] = suf;
    }
    __syncthreads();

    // Output tl = tid: window [tl, tl+256] local.
    const int tl = tid;
    const int c  = tl >> 4;                  // chunk of tl
    float m = sSuf[tl];                      // covers [tl, 16(c+1))
    #pragma unroll
    for (int k = 1; k <= 15; k++)            // full chunks c+1 .. c+15
        m = fminf(m, sPre[16 * (c + k) + 15]);
    m = fminf(m, sPre[tl + 256]);            // covers [16(c+16), tl+256]

    out[(size_t)b * T + t0 + tl] = m;
}

extern "C" void kernel_launch(void* const* d_in, const int* in_sizes, int n_in,
                              void* d_out, int out_size)
{
    const float* sig = (const float*)d_in[0];
    float* out = (float*)d_out;

    const int T = 8192;                      // per reference setup_inputs
    const int B = in_sizes[0] / T;           // = 4

    dim3 grid(T / BT, B);
    always_window_min<<<grid, BT>>>(sig, out, T);
}